// round 1
// baseline (speedup 1.0000x reference)
#include <cuda_runtime.h>
#include <cstdint>

#define TT 256
#define BB 64
#define DD 1024
#define HHID 1024
#define NG 4096           // 4*H, gate-interleaved columns (c = j*4 + g)
#define MBIG (TT*BB)      // 16384
#define NBLK_REC 128

// ---------------- device scratch (static globals: allowed) ----------------
__device__ float g_Wx[DD*NG];                 // tf32, interleaved  (16 MB)
__device__ float g_Wh[HHID*NG];               // tf32, interleaved  (16 MB)
__device__ float g_Wq[HHID*DD];               // tf32               (4 MB)
__device__ float g_b[NG];                     // fp32 packed biases
__device__ float g_Xg[(size_t)MBIG*NG];       // fp32 gate preacts  (256 MB)
__device__ float g_Htf[2][BB*HHID];           // tf32 H double buffer
__device__ float g_C[BB*HHID];                // fp32 C
__device__ float g_Hs[(size_t)MBIG*HHID];     // tf32 H history     (64 MB)
__device__ unsigned g_cnt;
__device__ volatile unsigned g_gen;

// ---------------- helpers ----------------
__device__ __forceinline__ float f2tf(float x) {
    unsigned u;
    asm("cvt.rna.tf32.f32 %0, %1;" : "=r"(u) : "f"(x));
    return __uint_as_float(u);
}

__device__ __forceinline__ void mma8(float* c, const unsigned* a, const unsigned* b) {
    asm volatile(
        "mma.sync.aligned.m16n8k8.row.col.f32.tf32.tf32.f32 "
        "{%0,%1,%2,%3},{%4,%5,%6,%7},{%8,%9},{%0,%1,%2,%3};\n"
        : "+f"(c[0]), "+f"(c[1]), "+f"(c[2]), "+f"(c[3])
        : "r"(a[0]), "r"(a[1]), "r"(a[2]), "r"(a[3]), "r"(b[0]), "r"(b[1]));
}

// ---------------- prep: pack + convert weights, init state ----------------
__global__ void prep_kernel(
    const float* __restrict__ Wxi, const float* __restrict__ Wxf,
    const float* __restrict__ Wxo, const float* __restrict__ Wxc,
    const float* __restrict__ Whi, const float* __restrict__ Whf,
    const float* __restrict__ Who, const float* __restrict__ Whc,
    const float* __restrict__ bi,  const float* __restrict__ bf_,
    const float* __restrict__ bo,  const float* __restrict__ bc,
    const float* __restrict__ Whq,
    const float* __restrict__ H0,  const float* __restrict__ C0)
{
    int i = blockIdx.x * 256 + threadIdx.x;     // 0 .. 1048575
    // W_x pack: src index i = k*1024 + j  ->  dst = k*4096 + j*4 + g = 4*i + g
    {
        float4 v = make_float4(f2tf(Wxi[i]), f2tf(Wxf[i]), f2tf(Wxo[i]), f2tf(Wxc[i]));
        *reinterpret_cast<float4*>(&g_Wx[(size_t)i * 4]) = v;
    }
    {
        float4 v = make_float4(f2tf(Whi[i]), f2tf(Whf[i]), f2tf(Who[i]), f2tf(Whc[i]));
        *reinterpret_cast<float4*>(&g_Wh[(size_t)i * 4]) = v;
    }
    g_Wq[i] = f2tf(Whq[i]);
    if (i < HHID) {
        g_b[i * 4 + 0] = bi[i];
        g_b[i * 4 + 1] = bf_[i];
        g_b[i * 4 + 2] = bo[i];
        g_b[i * 4 + 3] = bc[i];
    }
    if (i < BB * HHID) {
        g_Htf[0][i] = f2tf(H0[i]);
        g_C[i] = C0[i];
    }
}

// ---------------- big GEMM: C = A(MxK) @ B(KxN) + bias, tf32 MMA -------------
// mode 0: A=inputs(fp32,convert), B=g_Wx, bias=g_b,  C=g_Xg,  N=4096
// mode 1: A=g_Hs(tf32),           B=g_Wq, bias=barg, C=Carg,  N=1024
__global__ __launch_bounds__(256) void gemm_tf32(
    const float* __restrict__ Aarg, const float* __restrict__ barg,
    float* __restrict__ Carg, int mode)
{
    __shared__ float As[128][36];   // row-major [m][k], pad 36: conflict-free frags
    __shared__ float Bs[32][136];   // row-major [k][n], pad 136

    const float* A    = mode ? g_Hs : Aarg;
    const float* Bm   = mode ? g_Wq : g_Wx;
    const float* bias = mode ? barg : g_b;
    float*       C    = mode ? Carg : g_Xg;
    const int N = mode ? DD : NG;
    const int K = 1024;
    const int convA = (mode == 0);

    int tid  = threadIdx.x;
    int row0 = blockIdx.y * 128;
    int col0 = blockIdx.x * 128;
    int w = tid >> 5, lane = tid & 31, g = lane >> 2, tq = lane & 3;
    int wm = w & 3, wn = w >> 2;     // warp tile: rows 32*wm, cols 64*wn

    float acc[2][8][4];
#pragma unroll
    for (int a = 0; a < 2; a++)
#pragma unroll
        for (int b = 0; b < 8; b++)
#pragma unroll
            for (int c = 0; c < 4; c++) acc[a][b][c] = 0.f;

    for (int kc = 0; kc < K; kc += 32) {
        __syncthreads();
#pragma unroll
        for (int j = 0; j < 4; j++) {           // A: 128x32 = 1024 float4
            int idx = tid + j * 256;
            int r = idx >> 3, q = (idx & 7) * 4;
            float4 v = *reinterpret_cast<const float4*>(&A[(size_t)(row0 + r) * K + kc + q]);
            if (convA) { v.x = f2tf(v.x); v.y = f2tf(v.y); v.z = f2tf(v.z); v.w = f2tf(v.w); }
            As[r][q] = v.x; As[r][q + 1] = v.y; As[r][q + 2] = v.z; As[r][q + 3] = v.w;
        }
#pragma unroll
        for (int j = 0; j < 4; j++) {           // B: 32x128 = 1024 float4
            int idx = tid + j * 256;
            int r = idx >> 5, q = (idx & 31) * 4;
            float4 v = *reinterpret_cast<const float4*>(&Bm[(size_t)(kc + r) * N + col0 + q]);
            Bs[r][q] = v.x; Bs[r][q + 1] = v.y; Bs[r][q + 2] = v.z; Bs[r][q + 3] = v.w;
        }
        __syncthreads();

        const unsigned* Asu = reinterpret_cast<const unsigned*>(As);
        const unsigned* Bsu = reinterpret_cast<const unsigned*>(Bs);
#pragma unroll
        for (int ks = 0; ks < 32; ks += 8) {
            unsigned af[2][4], bfrag[8][2];
#pragma unroll
            for (int mt = 0; mt < 2; mt++) {
                int r = wm * 32 + mt * 16 + g;
                af[mt][0] = Asu[r * 36 + ks + tq];
                af[mt][1] = Asu[(r + 8) * 36 + ks + tq];
                af[mt][2] = Asu[r * 36 + ks + tq + 4];
                af[mt][3] = Asu[(r + 8) * 36 + ks + tq + 4];
            }
#pragma unroll
            for (int nt = 0; nt < 8; nt++) {
                int c = wn * 64 + nt * 8 + g;
                bfrag[nt][0] = Bsu[(ks + tq) * 136 + c];
                bfrag[nt][1] = Bsu[(ks + tq + 4) * 136 + c];
            }
#pragma unroll
            for (int mt = 0; mt < 2; mt++)
#pragma unroll
                for (int nt = 0; nt < 8; nt++)
                    mma8(acc[mt][nt], af[mt], bfrag[nt]);
        }
    }

#pragma unroll
    for (int mt = 0; mt < 2; mt++) {
        int r = row0 + wm * 32 + mt * 16 + g;
#pragma unroll
        for (int nt = 0; nt < 8; nt++) {
            int c = col0 + wn * 64 + nt * 8 + tq * 2;
            float b0 = bias[c], b1 = bias[c + 1];
            float2 v0 = make_float2(acc[mt][nt][0] + b0, acc[mt][nt][1] + b1);
            float2 v1 = make_float2(acc[mt][nt][2] + b0, acc[mt][nt][3] + b1);
            *reinterpret_cast<float2*>(&C[(size_t)r * N + c]) = v0;
            *reinterpret_cast<float2*>(&C[(size_t)(r + 8) * N + c]) = v1;
        }
    }
}

// ---------------- persistent recurrent kernel (128 blocks, all resident) ----
__global__ __launch_bounds__(256) void lstm_rec(float* __restrict__ out)
{
    __shared__ float As[64][68];    // A chunk [m][k], pad 68; reused as gate stage
    __shared__ float Bs[64][40];    // B chunk [k][n], pad 40
    float* Gs = &As[0][0];          // gate staging, stride 36 (2304 floats < 4352)

    int tid = threadIdx.x;
    int bcol = blockIdx.x * 32;     // gate-column base in [0,4096)
    int jg0  = blockIdx.x * 8;      // hidden-unit base in [0,1024)
    int w = tid >> 5, lane = tid & 31, g = lane >> 2, tq = lane & 3;
    int mt = w >> 1;                // 0..3: M tile (rows mt*16)
    int ntb = (w & 1) * 2;          // N tile base: 0 or 2

    for (int t = 0; t < TT; t++) {
        const float* Habuf = g_Htf[t & 1];
        float acc[2][4] = {{0.f, 0.f, 0.f, 0.f}, {0.f, 0.f, 0.f, 0.f}};

        for (int kc = 0; kc < HHID; kc += 64) {
            __syncthreads();
#pragma unroll
            for (int j = 0; j < 4; j++) {       // A: 64x64 = 1024 float4 (.cg!)
                int idx = tid + j * 256;
                int r = idx >> 4, q = (idx & 15) * 4;
                float4 v = __ldcg(reinterpret_cast<const float4*>(&Habuf[r * HHID + kc + q]));
                As[r][q] = v.x; As[r][q + 1] = v.y; As[r][q + 2] = v.z; As[r][q + 3] = v.w;
            }
#pragma unroll
            for (int j = 0; j < 2; j++) {       // B: 64x32 = 512 float4
                int idx = tid + j * 256;
                int r = idx >> 3, q = (idx & 7) * 4;
                float4 v = *reinterpret_cast<const float4*>(&g_Wh[(size_t)(kc + r) * NG + bcol + q]);
                Bs[r][q] = v.x; Bs[r][q + 1] = v.y; Bs[r][q + 2] = v.z; Bs[r][q + 3] = v.w;
            }
            __syncthreads();

            const unsigned* Asu = reinterpret_cast<const unsigned*>(As);
            const unsigned* Bsu = reinterpret_cast<const unsigned*>(Bs);
#pragma unroll
            for (int ks = 0; ks < 64; ks += 8) {
                unsigned af[4];
                int r = mt * 16 + g;
                af[0] = Asu[r * 68 + ks + tq];
                af[1] = Asu[(r + 8) * 68 + ks + tq];
                af[2] = Asu[r * 68 + ks + tq + 4];
                af[3] = Asu[(r + 8) * 68 + ks + tq + 4];
#pragma unroll
                for (int nn = 0; nn < 2; nn++) {
                    int c = (ntb + nn) * 8 + g;
                    unsigned bfrag[2] = { Bsu[(ks + tq) * 40 + c],
                                          Bsu[(ks + tq + 4) * 40 + c] };
                    mma8(acc[nn], af, bfrag);
                }
            }
        }
        __syncthreads();
        // stage gates to smem (stride 36)
#pragma unroll
        for (int nn = 0; nn < 2; nn++) {
            int r = mt * 16 + g, c = (ntb + nn) * 8 + tq * 2;
            *reinterpret_cast<float2*>(&Gs[r * 36 + c]) = make_float2(acc[nn][0], acc[nn][1]);
            *reinterpret_cast<float2*>(&Gs[(r + 8) * 36 + c]) = make_float2(acc[nn][2], acc[nn][3]);
        }
        __syncthreads();

        // pointwise: 512 (row, hidden) pairs, 2 per thread
#pragma unroll
        for (int p = tid; p < 512; p += 256) {
            int r = p >> 3, jl = p & 7;
            float4 xg = *reinterpret_cast<const float4*>(
                &g_Xg[((size_t)t * BB + r) * NG + bcol + jl * 4]);
            float gi = Gs[r * 36 + jl * 4 + 0] + xg.x;
            float gf = Gs[r * 36 + jl * 4 + 1] + xg.y;
            float go = Gs[r * 36 + jl * 4 + 2] + xg.z;
            float gc = Gs[r * 36 + jl * 4 + 3] + xg.w;
            float I  = 1.f / (1.f + __expf(-gi));
            float F  = 1.f / (1.f + __expf(-gf));
            float O  = 1.f / (1.f + __expf(-go));
            float Ct = tanhf(gc);
            int hidx = r * HHID + jg0 + jl;
            float Cn = F * g_C[hidx] + I * Ct;
            float Hn = O * tanhf(Cn);
            g_C[hidx] = Cn;
            float ht = f2tf(Hn);
            g_Htf[(t + 1) & 1][hidx] = ht;
            g_Hs[((size_t)t * BB + r) * HHID + jg0 + jl] = ht;
            if (t == TT - 1) {
                out[(size_t)MBIG * DD + hidx] = Hn;
                out[(size_t)MBIG * DD + BB * HHID + hidx] = Cn;
            }
        }

        // grid barrier
        __syncthreads();
        if (tid == 0) {
            __threadfence();
            unsigned gen = g_gen;
            if (atomicAdd(&g_cnt, 1u) == NBLK_REC - 1) {
                g_cnt = 0;
                __threadfence();
                g_gen = gen + 1;
            } else {
                while (g_gen == gen) { }
            }
        }
        __syncthreads();
    }
}

// ---------------- launch ----------------
extern "C" void kernel_launch(void* const* d_in, const int* in_sizes, int n_in,
                              void* d_out, int out_size)
{
    const float* inputs = (const float*)d_in[0];
    const float* H0  = (const float*)d_in[1];
    const float* C0  = (const float*)d_in[2];
    const float* Wxi = (const float*)d_in[3];
    const float* Whi = (const float*)d_in[4];
    const float* bi  = (const float*)d_in[5];
    const float* Wxf = (const float*)d_in[6];
    const float* Whf = (const float*)d_in[7];
    const float* bf_ = (const float*)d_in[8];
    const float* Wxo = (const float*)d_in[9];
    const float* Who = (const float*)d_in[10];
    const float* bo  = (const float*)d_in[11];
    const float* Wxc = (const float*)d_in[12];
    const float* Whc = (const float*)d_in[13];
    const float* bc  = (const float*)d_in[14];
    const float* Whq = (const float*)d_in[15];
    const float* bq  = (const float*)d_in[16];
    float* out = (float*)d_out;

    prep_kernel<<<4096, 256>>>(Wxi, Wxf, Wxo, Wxc, Whi, Whf, Who, Whc,
                               bi, bf_, bo, bc, Whq, H0, C0);
    gemm_tf32<<<dim3(32, 128), 256>>>(inputs, nullptr, nullptr, 0);   // Xg
    lstm_rec<<<NBLK_REC, 256>>>(out);                                 // recurrence
    gemm_tf32<<<dim3(8, 128), 256>>>(nullptr, bq, out, 1);            // outputs
}

// round 2
// speedup vs baseline: 2.0756x; 2.0756x over previous
#include <cuda_runtime.h>
#include <cstdint>

#define TT 256
#define BB 64
#define DD 1024
#define HHID 1024
#define NG 4096           // 4*H, gate-interleaved columns (c = j*4 + g)
#define MBIG (TT*BB)      // 16384
#define NBLK_REC 128

// Dynamic smem layout for lstm_rec (floats):
//   [0, 32768)          Whf slice (frag-ordered, 128 KB)
//   [32768, 49152)      A double buffer (2 x 8192 floats = 2 x 32 KB)
//   [49152, 51456)      gate staging, stride 36 (64 x 36)
#define SM_WHF 0
#define SM_ABUF 32768
#define SM_GS  49152
#define SMEM_REC_BYTES ((49152 + 64*36) * 4)

// ---------------- device scratch ----------------
__device__ float g_Wx[DD*NG];                 // tf32, interleaved  (16 MB)
__device__ float g_Whf[HHID*NG];              // tf32, FRAG-ordered (16 MB)
__device__ float g_Wq[HHID*DD];               // tf32               (4 MB)
__device__ float g_b[NG];                     // fp32 packed biases
__device__ float g_Xg[(size_t)MBIG*NG];       // fp32 gate preacts  (256 MB)
__device__ float g_Htf[2][BB*HHID];           // tf32 H double buffer, FRAG-ordered
__device__ float g_Hs[(size_t)MBIG*HHID];     // tf32 H history (normal [t][r][k])
__device__ unsigned g_cnt;
__device__ volatile unsigned g_gen;

// ---------------- helpers ----------------
__device__ __forceinline__ float f2tf(float x) {
    unsigned u;
    asm("cvt.rna.tf32.f32 %0, %1;" : "=r"(u) : "f"(x));
    return __uint_as_float(u);
}

__device__ __forceinline__ void mma8(float* c, const unsigned* a, const unsigned* b) {
    asm volatile(
        "mma.sync.aligned.m16n8k8.row.col.f32.tf32.tf32.f32 "
        "{%0,%1,%2,%3},{%4,%5,%6,%7},{%8,%9},{%0,%1,%2,%3};\n"
        : "+f"(c[0]), "+f"(c[1]), "+f"(c[2]), "+f"(c[3])
        : "r"(a[0]), "r"(a[1]), "r"(a[2]), "r"(a[3]), "r"(b[0]), "r"(b[1]));
}

__device__ __forceinline__ void cpa16(uint32_t d, const void* s) {
    asm volatile("cp.async.cg.shared.global [%0], [%1], 16;\n" :: "r"(d), "l"(s));
}
#define CPA_COMMIT()  asm volatile("cp.async.commit_group;\n")
#define CPA_WAIT(N)   asm volatile("cp.async.wait_group %0;\n" :: "n"(N))

// Frag index of H element (row r in [0,64), hidden k in [0,1024)):
// kb=k>>3, mt=r>>4, g=r&7, half=(r>>3)&1, tq=k&3, kh=(k>>2)&1
// idx = ((kb*4+mt)*32 + g*4+tq)*4 + half + 2*kh
__device__ __forceinline__ int hfrag_idx(int r, int k) {
    int kb = k >> 3, mt = r >> 4, g = r & 7, half = (r >> 3) & 1;
    int tq = k & 3, kh = (k >> 2) & 1;
    return ((kb * 4 + mt) * 32 + g * 4 + tq) * 4 + half + 2 * kh;
}

// ---------------- prep: pack + convert weights, init state ----------------
__global__ void prep_kernel(
    const float* __restrict__ Wxi, const float* __restrict__ Wxf,
    const float* __restrict__ Wxo, const float* __restrict__ Wxc,
    const float* __restrict__ Whi, const float* __restrict__ Whf_,
    const float* __restrict__ Who, const float* __restrict__ Whc,
    const float* __restrict__ bi,  const float* __restrict__ bf_,
    const float* __restrict__ bo,  const float* __restrict__ bc,
    const float* __restrict__ Whq, const float* __restrict__ H0)
{
    int i = blockIdx.x * 256 + threadIdx.x;     // 0 .. 1048575
    // W_x pack: src (k, j) -> dst col c = j*4+g: dst = 4*i + g
    {
        float4 v = make_float4(f2tf(Wxi[i]), f2tf(Wxf[i]), f2tf(Wxo[i]), f2tf(Wxc[i]));
        *reinterpret_cast<float4*>(&g_Wx[(size_t)i * 4]) = v;
    }
    // W_h frag pack: element (k, c=j*4+g) ->
    //   b=c>>5, kb=k>>3, ntl=(c>>3)&3, gg=c&7, tq=k&3, kh=(k>>2)&1
    //   dst = (((b*128 + kb)*4 + ntl)*32 + gg*4 + tq)*2 + kh
    {
        int k = i >> 10, j = i & 1023;
        float v[4] = { f2tf(Whi[i]), f2tf(Whf_[i]), f2tf(Who[i]), f2tf(Whc[i]) };
        int kb = k >> 3, tq = k & 3, kh = (k >> 2) & 1;
#pragma unroll
        for (int g = 0; g < 4; g++) {
            int c = j * 4 + g;
            int b = c >> 5, ntl = (c >> 3) & 3, gg = c & 7;
            size_t dst = ((((size_t)b * 128 + kb) * 4 + ntl) * 32 + gg * 4 + tq) * 2 + kh;
            g_Whf[dst] = v[g];
        }
    }
    g_Wq[i] = f2tf(Whq[i]);
    if (i < HHID) {
        g_b[i * 4 + 0] = bi[i];
        g_b[i * 4 + 1] = bf_[i];
        g_b[i * 4 + 2] = bo[i];
        g_b[i * 4 + 3] = bc[i];
    }
    if (i < BB * HHID) {
        int r = i >> 10, k = i & 1023;
        g_Htf[0][hfrag_idx(r, k)] = f2tf(H0[i]);
    }
}

// ---------------- big GEMM: C = A(MxK) @ B(KxN) + bias, tf32 MMA -------------
__global__ __launch_bounds__(256) void gemm_tf32(
    const float* __restrict__ Aarg, const float* __restrict__ barg,
    float* __restrict__ Carg, int mode)
{
    __shared__ float As[128][36];
    __shared__ float Bs[32][136];

    const float* A    = mode ? g_Hs : Aarg;
    const float* Bm   = mode ? g_Wq : g_Wx;
    const float* bias = mode ? barg : g_b;
    float*       C    = mode ? Carg : g_Xg;
    const int N = mode ? DD : NG;
    const int K = 1024;
    const int convA = (mode == 0);

    int tid  = threadIdx.x;
    int row0 = blockIdx.y * 128;
    int col0 = blockIdx.x * 128;
    int w = tid >> 5, lane = tid & 31, g = lane >> 2, tq = lane & 3;
    int wm = w & 3, wn = w >> 2;

    float acc[2][8][4];
#pragma unroll
    for (int a = 0; a < 2; a++)
#pragma unroll
        for (int b = 0; b < 8; b++)
#pragma unroll
            for (int c = 0; c < 4; c++) acc[a][b][c] = 0.f;

    for (int kc = 0; kc < K; kc += 32) {
        __syncthreads();
#pragma unroll
        for (int j = 0; j < 4; j++) {
            int idx = tid + j * 256;
            int r = idx >> 3, q = (idx & 7) * 4;
            float4 v = *reinterpret_cast<const float4*>(&A[(size_t)(row0 + r) * K + kc + q]);
            if (convA) { v.x = f2tf(v.x); v.y = f2tf(v.y); v.z = f2tf(v.z); v.w = f2tf(v.w); }
            As[r][q] = v.x; As[r][q + 1] = v.y; As[r][q + 2] = v.z; As[r][q + 3] = v.w;
        }
#pragma unroll
        for (int j = 0; j < 4; j++) {
            int idx = tid + j * 256;
            int r = idx >> 5, q = (idx & 31) * 4;
            float4 v = *reinterpret_cast<const float4*>(&Bm[(size_t)(kc + r) * N + col0 + q]);
            Bs[r][q] = v.x; Bs[r][q + 1] = v.y; Bs[r][q + 2] = v.z; Bs[r][q + 3] = v.w;
        }
        __syncthreads();

        const unsigned* Asu = reinterpret_cast<const unsigned*>(As);
        const unsigned* Bsu = reinterpret_cast<const unsigned*>(Bs);
#pragma unroll
        for (int ks = 0; ks < 32; ks += 8) {
            unsigned af[2][4], bfrag[8][2];
#pragma unroll
            for (int mt = 0; mt < 2; mt++) {
                int r = wm * 32 + mt * 16 + g;
                af[mt][0] = Asu[r * 36 + ks + tq];
                af[mt][1] = Asu[(r + 8) * 36 + ks + tq];
                af[mt][2] = Asu[r * 36 + ks + tq + 4];
                af[mt][3] = Asu[(r + 8) * 36 + ks + tq + 4];
            }
#pragma unroll
            for (int nt = 0; nt < 8; nt++) {
                int c = wn * 64 + nt * 8 + g;
                bfrag[nt][0] = Bsu[(ks + tq) * 136 + c];
                bfrag[nt][1] = Bsu[(ks + tq + 4) * 136 + c];
            }
#pragma unroll
            for (int mt = 0; mt < 2; mt++)
#pragma unroll
                for (int nt = 0; nt < 8; nt++)
                    mma8(acc[mt][nt], af[mt], bfrag[nt]);
        }
    }

#pragma unroll
    for (int mt = 0; mt < 2; mt++) {
        int r = row0 + wm * 32 + mt * 16 + g;
#pragma unroll
        for (int nt = 0; nt < 8; nt++) {
            int c = col0 + wn * 64 + nt * 8 + tq * 2;
            float b0 = bias[c], b1 = bias[c + 1];
            float2 v0 = make_float2(acc[mt][nt][0] + b0, acc[mt][nt][1] + b1);
            float2 v1 = make_float2(acc[mt][nt][2] + b0, acc[mt][nt][3] + b1);
            *reinterpret_cast<float2*>(&C[(size_t)r * N + c]) = v0;
            *reinterpret_cast<float2*>(&C[(size_t)(r + 8) * N + c]) = v1;
        }
    }
}

// ---------------- persistent recurrent kernel (128 blocks, 1/SM) ----------
__global__ __launch_bounds__(256, 1) void lstm_rec(const float* __restrict__ C0,
                                                   float* __restrict__ out)
{
    extern __shared__ float dsm[];
    float* whf  = dsm + SM_WHF;     // 32768 floats, frag-ordered Wh slice
    float* abuf = dsm + SM_ABUF;    // 2 x 8192 floats
    float* gs   = dsm + SM_GS;      // 64 x 36 gate stage

    const int tid = threadIdx.x;
    const int b   = blockIdx.x;
    const int bcol = b * 32;        // gate-column base in [0,4096)
    const int jg0  = b * 8;         // hidden-unit base in [0,1024)
    const int lane = tid & 31;
    const int w = tid >> 5;
    const int mt  = w >> 1;         // M tile (rows mt*16 .. +15)
    const int ntb = (w & 1) * 2;    // N tile base (cols ntb*8 .. +15)
    const int aoff = mt * 32 + lane;        // uint4 offset within kb slab
    const int boff = ntb * 32 + lane;       // uint2 offset within kb slab

    // --- load Wh slice into smem once (one cp.async group) ---
    {
        const float4* src = reinterpret_cast<const float4*>(g_Whf + (size_t)b * 32768);
        uint32_t dst = (uint32_t)__cvta_generic_to_shared(whf);
#pragma unroll
        for (int i = 0; i < 32; i++)
            cpa16(dst + (tid + i * 256) * 16, src + tid + i * 256);
        CPA_COMMIT();
    }

    // --- per-thread pointwise geometry (p = tid and tid+256) ---
    const int r0 = tid >> 3,          jl0 = tid & 7;
    const int r1 = (tid + 256) >> 3,  jl1 = tid & 7;
    const int k0 = jg0 + jl0, k1 = jg0 + jl1;
    const int hfi0 = hfrag_idx(r0, k0), hfi1 = hfrag_idx(r1, k1);
    float Creg0 = C0[r0 * HHID + k0];
    float Creg1 = C0[r1 * HHID + k1];

    const uint32_t abase = (uint32_t)__cvta_generic_to_shared(abuf);

    for (int t = 0; t < TT; t++) {
        const float* Hsrc = g_Htf[t & 1];
        float* Hdst = g_Htf[(t + 1) & 1];

        // Xg prefetch into registers (DRAM, single use)
        float4 xg0 = __ldcg(reinterpret_cast<const float4*>(
            &g_Xg[((size_t)t * BB + r0) * NG + bcol + jl0 * 4]));
        float4 xg1 = __ldcg(reinterpret_cast<const float4*>(
            &g_Xg[((size_t)t * BB + r1) * NG + bcol + jl1 * 4]));

        // issue H chunks 0,1 (each 8192 floats = 32 KB)
#pragma unroll
        for (int c = 0; c < 2; c++) {
            const float4* src = reinterpret_cast<const float4*>(Hsrc + c * 8192);
            uint32_t dst = abase + (uint32_t)(c & 1) * 32768u;
#pragma unroll
            for (int i = 0; i < 8; i++)
                cpa16(dst + (tid + i * 256) * 16, src + tid + i * 256);
            CPA_COMMIT();
        }

        float acc[2][4] = {{0.f,0.f,0.f,0.f},{0.f,0.f,0.f,0.f}};

#pragma unroll
        for (int c = 0; c < 8; c++) {
            if (c < 7) { CPA_WAIT(1); } else { CPA_WAIT(0); }
            __syncthreads();
            const uint4* Ap = reinterpret_cast<const uint4*>(abuf + (c & 1) * 8192);
            const uint2* Bp = reinterpret_cast<const uint2*>(whf) + (size_t)(c * 16) * 128;
#pragma unroll
            for (int kb = 0; kb < 16; kb++) {
                uint4 av = Ap[kb * 128 + aoff];
                unsigned af[4] = { av.x, av.y, av.z, av.w };
                uint2 bv0 = Bp[kb * 128 + boff];
                uint2 bv1 = Bp[kb * 128 + boff + 32];
                mma8(acc[0], af, reinterpret_cast<unsigned*>(&bv0));
                mma8(acc[1], af, reinterpret_cast<unsigned*>(&bv1));
            }
            __syncthreads();
            if (c + 2 < 8) {
                int cn = c + 2;
                const float4* src = reinterpret_cast<const float4*>(Hsrc + cn * 8192);
                uint32_t dst = abase + (uint32_t)(cn & 1) * 32768u;
#pragma unroll
                for (int i = 0; i < 8; i++)
                    cpa16(dst + (tid + i * 256) * 16, src + tid + i * 256);
                CPA_COMMIT();
            }
        }

        // stage gates (rows mt*16+g / +8, cols (ntb+nn)*8 + tq*2)
        {
            int g = lane >> 2, tq = lane & 3;
#pragma unroll
            for (int nn = 0; nn < 2; nn++) {
                int r = mt * 16 + g, cc = (ntb + nn) * 8 + tq * 2;
                *reinterpret_cast<float2*>(&gs[r * 36 + cc]) =
                    make_float2(acc[nn][0], acc[nn][1]);
                *reinterpret_cast<float2*>(&gs[(r + 8) * 36 + cc]) =
                    make_float2(acc[nn][2], acc[nn][3]);
            }
        }
        __syncthreads();

        // pointwise: 2 hidden units per thread
#pragma unroll
        for (int q = 0; q < 2; q++) {
            int r  = q ? r1 : r0;
            int jl = q ? jl1 : jl0;
            float4 xg = q ? xg1 : xg0;
            float gi = gs[r * 36 + jl * 4 + 0] + xg.x;
            float gf = gs[r * 36 + jl * 4 + 1] + xg.y;
            float go = gs[r * 36 + jl * 4 + 2] + xg.z;
            float gc = gs[r * 36 + jl * 4 + 3] + xg.w;
            float I  = 1.f / (1.f + __expf(-gi));
            float F  = 1.f / (1.f + __expf(-gf));
            float O  = 1.f / (1.f + __expf(-go));
            float Ct = tanhf(gc);
            float Cc = q ? Creg1 : Creg0;
            float Cn = F * Cc + I * Ct;
            float Hn = O * tanhf(Cn);
            if (q) Creg1 = Cn; else Creg0 = Cn;
            float ht = f2tf(Hn);
            Hdst[q ? hfi1 : hfi0] = ht;
            int kg = q ? k1 : k0;
            g_Hs[((size_t)t * BB + r) * HHID + kg] = ht;
            if (t == TT - 1) {
                out[(size_t)MBIG * DD + r * HHID + kg] = Hn;
                out[(size_t)MBIG * DD + BB * HHID + r * HHID + kg] = Cn;
            }
        }

        // grid barrier (release: all threads fence so H writes are L2-visible)
        __threadfence();
        __syncthreads();
        if (tid == 0) {
            unsigned gen = g_gen;
            if (atomicAdd(&g_cnt, 1u) == NBLK_REC - 1) {
                g_cnt = 0;
                __threadfence();
                g_gen = gen + 1;
            } else {
                while (g_gen == gen) { }
            }
        }
        __syncthreads();
    }
}

// ---------------- launch ----------------
extern "C" void kernel_launch(void* const* d_in, const int* in_sizes, int n_in,
                              void* d_out, int out_size)
{
    const float* inputs = (const float*)d_in[0];
    const float* H0  = (const float*)d_in[1];
    const float* C0  = (const float*)d_in[2];
    const float* Wxi = (const float*)d_in[3];
    const float* Whi = (const float*)d_in[4];
    const float* bi  = (const float*)d_in[5];
    const float* Wxf = (const float*)d_in[6];
    const float* Whf = (const float*)d_in[7];
    const float* bf_ = (const float*)d_in[8];
    const float* Wxo = (const float*)d_in[9];
    const float* Who = (const float*)d_in[10];
    const float* bo  = (const float*)d_in[11];
    const float* Wxc = (const float*)d_in[12];
    const float* Whc = (const float*)d_in[13];
    const float* bc  = (const float*)d_in[14];
    const float* Whq = (const float*)d_in[15];
    const float* bq  = (const float*)d_in[16];
    float* out = (float*)d_out;

    cudaFuncSetAttribute(lstm_rec, cudaFuncAttributeMaxDynamicSharedMemorySize,
                         SMEM_REC_BYTES);

    prep_kernel<<<4096, 256>>>(Wxi, Wxf, Wxo, Wxc, Whi, Whf, Who, Whc,
                               bi, bf_, bo, bc, Whq, H0);
    gemm_tf32<<<dim3(32, 128), 256>>>(inputs, nullptr, nullptr, 0);   // Xg
    lstm_rec<<<NBLK_REC, 256, SMEM_REC_BYTES>>>(C0, out);             // recurrence
    gemm_tf32<<<dim3(8, 128), 256>>>(nullptr, bq, out, 1);            // outputs
}

// round 3
// speedup vs baseline: 2.1302x; 1.0263x over previous
#include <cuda_runtime.h>
#include <cstdint>

#define TT 256
#define BB 64
#define DD 1024
#define HHID 1024
#define NG 4096           // 4*H, gate-interleaved columns (c = j*4 + g)
#define MBIG (TT*BB)      // 16384
#define NBLK_REC 128

// Dynamic smem layout for lstm_rec (floats):
//   [0, 32768)          Whf slice (frag-ordered, 128 KB)
//   [32768, 49152)      A double buffer (2 x 8192 floats); reused for reduction
//   [49152, 51456)      gate staging, stride 36 (64 x 36)
#define SM_WHF 0
#define SM_ABUF 32768
#define SM_GS  49152
#define SMEM_REC_BYTES ((49152 + 64*36) * 4)

// ---------------- device scratch ----------------
__device__ float g_Wx[DD*NG];                 // tf32, interleaved  (16 MB)
__device__ float g_Whf[HHID*NG];              // tf32, FRAG-ordered (16 MB)
__device__ float g_Wq[HHID*DD];               // tf32               (4 MB)
__device__ float g_b[NG];                     // fp32 packed biases
__device__ float g_Xg[(size_t)MBIG*NG];       // fp32 gate preacts  (256 MB)
__device__ float g_Htf[2][BB*HHID];           // tf32 H double buffer, FRAG-ordered
__device__ float g_Hs[(size_t)MBIG*HHID];     // tf32 H history (normal [t][r][k])
__device__ unsigned g_ck[8];                  // per-chunk publish counters

// ---------------- helpers ----------------
__device__ __forceinline__ float f2tf(float x) {
    unsigned u;
    asm("cvt.rna.tf32.f32 %0, %1;" : "=r"(u) : "f"(x));
    return __uint_as_float(u);
}

__device__ __forceinline__ void mma8(float* c, const unsigned* a, const unsigned* b) {
    asm volatile(
        "mma.sync.aligned.m16n8k8.row.col.f32.tf32.tf32.f32 "
        "{%0,%1,%2,%3},{%4,%5,%6,%7},{%8,%9},{%0,%1,%2,%3};\n"
        : "+f"(c[0]), "+f"(c[1]), "+f"(c[2]), "+f"(c[3])
        : "r"(a[0]), "r"(a[1]), "r"(a[2]), "r"(a[3]), "r"(b[0]), "r"(b[1]));
}

__device__ __forceinline__ void cpa16(uint32_t d, const void* s) {
    asm volatile("cp.async.cg.shared.global [%0], [%1], 16;\n" :: "r"(d), "l"(s));
}
#define CPA_COMMIT()  asm volatile("cp.async.commit_group;\n")
#define CPA_WAIT(N)   asm volatile("cp.async.wait_group %0;\n" :: "n"(N))

__device__ __forceinline__ void poll_chunk(int c, unsigned target) {
    if (target == 0u) return;
    const unsigned* p = &g_ck[c];
    unsigned v;
    while (true) {
        asm volatile("ld.acquire.gpu.u32 %0, [%1];" : "=r"(v) : "l"(p));
        if (v >= target) break;
        __nanosleep(32);
    }
}

// Frag index of H element (row r in [0,64), hidden k in [0,1024)):
__device__ __forceinline__ int hfrag_idx(int r, int k) {
    int kb = k >> 3, mt = r >> 4, g = r & 7, half = (r >> 3) & 1;
    int tq = k & 3, kh = (k >> 2) & 1;
    return ((kb * 4 + mt) * 32 + g * 4 + tq) * 4 + half + 2 * kh;
}

// ---------------- prep: pack + convert weights, init state ----------------
__global__ void prep_kernel(
    const float* __restrict__ Wxi, const float* __restrict__ Wxf,
    const float* __restrict__ Wxo, const float* __restrict__ Wxc,
    const float* __restrict__ Whi, const float* __restrict__ Whf_,
    const float* __restrict__ Who, const float* __restrict__ Whc,
    const float* __restrict__ bi,  const float* __restrict__ bf_,
    const float* __restrict__ bo,  const float* __restrict__ bc,
    const float* __restrict__ Whq, const float* __restrict__ H0)
{
    int i = blockIdx.x * 256 + threadIdx.x;     // 0 .. 1048575
    {
        float4 v = make_float4(f2tf(Wxi[i]), f2tf(Wxf[i]), f2tf(Wxo[i]), f2tf(Wxc[i]));
        *reinterpret_cast<float4*>(&g_Wx[(size_t)i * 4]) = v;
    }
    {
        int k = i >> 10, j = i & 1023;
        float v[4] = { f2tf(Whi[i]), f2tf(Whf_[i]), f2tf(Who[i]), f2tf(Whc[i]) };
        int kb = k >> 3, tq = k & 3, kh = (k >> 2) & 1;
#pragma unroll
        for (int g = 0; g < 4; g++) {
            int c = j * 4 + g;
            int b = c >> 5, ntl = (c >> 3) & 3, gg = c & 7;
            size_t dst = ((((size_t)b * 128 + kb) * 4 + ntl) * 32 + gg * 4 + tq) * 2 + kh;
            g_Whf[dst] = v[g];
        }
    }
    g_Wq[i] = f2tf(Whq[i]);
    if (i < HHID) {
        g_b[i * 4 + 0] = bi[i];
        g_b[i * 4 + 1] = bf_[i];
        g_b[i * 4 + 2] = bo[i];
        g_b[i * 4 + 3] = bc[i];
    }
    if (i < BB * HHID) {
        int r = i >> 10, k = i & 1023;
        g_Htf[0][hfrag_idx(r, k)] = f2tf(H0[i]);
    }
    if (i < 8) g_ck[i] = 0u;    // reset publish counters (every graph replay)
}

// ---------------- big GEMM: C = A(MxK) @ B(KxN) + bias, tf32 MMA -------------
__global__ __launch_bounds__(256, 2) void gemm_tf32(
    const float* __restrict__ Aarg, const float* __restrict__ barg,
    float* __restrict__ Carg, int mode)
{
    __shared__ float As[128][36];
    __shared__ float Bs[32][136];

    const float* A    = mode ? g_Hs : Aarg;
    const float* Bm   = mode ? g_Wq : g_Wx;
    const float* bias = mode ? barg : g_b;
    float*       C    = mode ? Carg : g_Xg;
    const int N = mode ? DD : NG;
    const int K = 1024;
    const int convA = (mode == 0);

    int tid  = threadIdx.x;
    int row0 = blockIdx.y * 128;
    int col0 = blockIdx.x * 128;
    int w = tid >> 5, lane = tid & 31, g = lane >> 2, tq = lane & 3;
    int wm = w & 3, wn = w >> 2;

    float acc[2][8][4];
#pragma unroll
    for (int a = 0; a < 2; a++)
#pragma unroll
        for (int b = 0; b < 8; b++)
#pragma unroll
            for (int c = 0; c < 4; c++) acc[a][b][c] = 0.f;

    for (int kc = 0; kc < K; kc += 32) {
        __syncthreads();
#pragma unroll
        for (int j = 0; j < 4; j++) {
            int idx = tid + j * 256;
            int r = idx >> 3, q = (idx & 7) * 4;
            float4 v = *reinterpret_cast<const float4*>(&A[(size_t)(row0 + r) * K + kc + q]);
            if (convA) { v.x = f2tf(v.x); v.y = f2tf(v.y); v.z = f2tf(v.z); v.w = f2tf(v.w); }
            As[r][q] = v.x; As[r][q + 1] = v.y; As[r][q + 2] = v.z; As[r][q + 3] = v.w;
        }
#pragma unroll
        for (int j = 0; j < 4; j++) {
            int idx = tid + j * 256;
            int r = idx >> 5, q = (idx & 31) * 4;
            float4 v = *reinterpret_cast<const float4*>(&Bm[(size_t)(kc + r) * N + col0 + q]);
            Bs[r][q] = v.x; Bs[r][q + 1] = v.y; Bs[r][q + 2] = v.z; Bs[r][q + 3] = v.w;
        }
        __syncthreads();

        const unsigned* Asu = reinterpret_cast<const unsigned*>(As);
        const unsigned* Bsu = reinterpret_cast<const unsigned*>(Bs);
#pragma unroll
        for (int ks = 0; ks < 32; ks += 8) {
            unsigned af[2][4], bfrag[8][2];
#pragma unroll
            for (int mt = 0; mt < 2; mt++) {
                int r = wm * 32 + mt * 16 + g;
                af[mt][0] = Asu[r * 36 + ks + tq];
                af[mt][1] = Asu[(r + 8) * 36 + ks + tq];
                af[mt][2] = Asu[r * 36 + ks + tq + 4];
                af[mt][3] = Asu[(r + 8) * 36 + ks + tq + 4];
            }
#pragma unroll
            for (int nt = 0; nt < 8; nt++) {
                int c = wn * 64 + nt * 8 + g;
                bfrag[nt][0] = Bsu[(ks + tq) * 136 + c];
                bfrag[nt][1] = Bsu[(ks + tq + 4) * 136 + c];
            }
#pragma unroll
            for (int mt = 0; mt < 2; mt++)
#pragma unroll
                for (int nt = 0; nt < 8; nt++)
                    mma8(acc[mt][nt], af[mt], bfrag[nt]);
        }
    }

#pragma unroll
    for (int mt = 0; mt < 2; mt++) {
        int r = row0 + wm * 32 + mt * 16 + g;
#pragma unroll
        for (int nt = 0; nt < 8; nt++) {
            int c = col0 + wn * 64 + nt * 8 + tq * 2;
            float b0 = bias[c], b1 = bias[c + 1];
            float2 v0 = make_float2(acc[mt][nt][0] + b0, acc[mt][nt][1] + b1);
            float2 v1 = make_float2(acc[mt][nt][2] + b0, acc[mt][nt][3] + b1);
            *reinterpret_cast<float2*>(&C[(size_t)r * N + c]) = v0;
            *reinterpret_cast<float2*>(&C[(size_t)(r + 8) * N + c]) = v1;
        }
    }
}

// ---------------- persistent recurrent kernel (128 blocks, 1/SM) ----------
// Warp layout: w = kgroup*2 + mh;  kgroup = w>>1 in [0,4): quarter of each
// chunk's k-steps;  mh = w&1: rows [mh*32, mh*32+32).  Each warp computes a
// 32x32 partial (2 m16 x 4 n8 tiles) -> 2-round smem tree reduction.
__global__ __launch_bounds__(256, 1) void lstm_rec(const float* __restrict__ C0,
                                                   float* __restrict__ out)
{
    extern __shared__ float dsm[];
    float* whf  = dsm + SM_WHF;     // 32768 floats, frag-ordered Wh slice
    float* abuf = dsm + SM_ABUF;    // 2 x 8192 floats (also reduction scratch)
    float* gs   = dsm + SM_GS;      // 64 x 36 gate stage

    const int tid = threadIdx.x;
    const int b   = blockIdx.x;
    const int bcol = b * 32;        // gate-column base in [0,4096)
    const int jg0  = b * 8;         // hidden-unit base in [0,1024)
    const int mychunk = b >> 4;     // chunk this block's H slice belongs to
    const int lane = tid & 31;
    const int w = tid >> 5;
    const int kgroup = w >> 1;      // 0..3
    const int mh = w & 1;           // row half

    // --- load Wh slice into smem once ---
    {
        const float4* src = reinterpret_cast<const float4*>(g_Whf + (size_t)b * 32768);
        uint32_t dst = (uint32_t)__cvta_generic_to_shared(whf);
#pragma unroll
        for (int i = 0; i < 32; i++)
            cpa16(dst + (tid + i * 256) * 16, src + tid + i * 256);
        CPA_COMMIT();
    }

    // --- per-thread pointwise geometry ---
    const int r0 = tid >> 3,          jl0 = tid & 7;
    const int r1 = (tid + 256) >> 3,  jl1 = tid & 7;
    const int k0 = jg0 + jl0, k1 = jg0 + jl1;
    const int hfi0 = hfrag_idx(r0, k0), hfi1 = hfrag_idx(r1, k1);
    float Creg0 = C0[r0 * HHID + k0];
    float Creg1 = C0[r1 * HHID + k1];

    const uint32_t abase = (uint32_t)__cvta_generic_to_shared(abuf);

    for (int t = 0; t < TT; t++) {
        const float* Hsrc = g_Htf[t & 1];
        float* Hdst = g_Htf[(t + 1) & 1];
        const unsigned target = 16u * (unsigned)t;

        // Xg prefetch into registers (DRAM, single use)
        float4 xg0 = __ldcg(reinterpret_cast<const float4*>(
            &g_Xg[((size_t)t * BB + r0) * NG + bcol + jl0 * 4]));
        float4 xg1 = __ldcg(reinterpret_cast<const float4*>(
            &g_Xg[((size_t)t * BB + r1) * NG + bcol + jl1 * 4]));

        // issue H chunks 0,1 after their producers have published
#pragma unroll
        for (int c = 0; c < 2; c++) {
            poll_chunk(c, target);
            const float4* src = reinterpret_cast<const float4*>(Hsrc + c * 8192);
            uint32_t dst = abase + (uint32_t)(c & 1) * 32768u;
#pragma unroll
            for (int i = 0; i < 8; i++)
                cpa16(dst + (tid + i * 256) * 16, src + tid + i * 256);
            CPA_COMMIT();
        }

        float acc[2][4][4];
#pragma unroll
        for (int a = 0; a < 2; a++)
#pragma unroll
            for (int n = 0; n < 4; n++)
#pragma unroll
                for (int e = 0; e < 4; e++) acc[a][n][e] = 0.f;

#pragma unroll
        for (int c = 0; c < 8; c++) {
            if (c < 7) { CPA_WAIT(1); } else { CPA_WAIT(0); }
            __syncthreads();
            const uint4* Ap = reinterpret_cast<const uint4*>(abuf + (c & 1) * 8192);
            const uint2* Bp = reinterpret_cast<const uint2*>(whf) + (size_t)(c * 16) * 128;
#pragma unroll
            for (int kk = 0; kk < 4; kk++) {
                int kb = kgroup * 4 + kk;
                uint4 a0 = Ap[kb * 128 + (mh * 2 + 0) * 32 + lane];
                uint4 a1 = Ap[kb * 128 + (mh * 2 + 1) * 32 + lane];
                unsigned af0[4] = { a0.x, a0.y, a0.z, a0.w };
                unsigned af1[4] = { a1.x, a1.y, a1.z, a1.w };
#pragma unroll
                for (int nt = 0; nt < 4; nt++) {
                    uint2 bv = Bp[kb * 128 + nt * 32 + lane];
                    mma8(acc[0][nt], af0, reinterpret_cast<unsigned*>(&bv));
                    mma8(acc[1][nt], af1, reinterpret_cast<unsigned*>(&bv));
                }
            }
            __syncthreads();
            if (c + 2 < 8) {
                int cn = c + 2;
                poll_chunk(cn, target);
                const float4* src = reinterpret_cast<const float4*>(Hsrc + cn * 8192);
                uint32_t dst = abase + (uint32_t)(cn & 1) * 32768u;
#pragma unroll
                for (int i = 0; i < 8; i++)
                    cpa16(dst + (tid + i * 256) * 16, src + tid + i * 256);
                CPA_COMMIT();
            }
        }

        // --- K-group reduction: 4 partials -> 1 (reuse abuf) ---
        float* red = abuf;
        if (w >= 4) {                      // kgroups 2,3 store (slots w-4 = 0..3)
            float* base = red + (w - 4) * 1024;
#pragma unroll
            for (int mi = 0; mi < 2; mi++)
#pragma unroll
                for (int nt = 0; nt < 4; nt++)
                    *reinterpret_cast<float4*>(&base[(mi * 4 + nt) * 128 + lane * 4]) =
                        *reinterpret_cast<float4*>(acc[mi][nt]);
        }
        __syncthreads();
        if (w < 4) {                       // kgroups 0,1 add partner (slot w)
            float* base = red + w * 1024;
#pragma unroll
            for (int mi = 0; mi < 2; mi++)
#pragma unroll
                for (int nt = 0; nt < 4; nt++) {
                    float4 v = *reinterpret_cast<float4*>(&base[(mi * 4 + nt) * 128 + lane * 4]);
                    acc[mi][nt][0] += v.x; acc[mi][nt][1] += v.y;
                    acc[mi][nt][2] += v.z; acc[mi][nt][3] += v.w;
                }
        }
        __syncthreads();
        if (w == 2 || w == 3) {            // kgroup 1 stores (slots w-2 = 0,1)
            float* base = red + (w - 2) * 1024;
#pragma unroll
            for (int mi = 0; mi < 2; mi++)
#pragma unroll
                for (int nt = 0; nt < 4; nt++)
                    *reinterpret_cast<float4*>(&base[(mi * 4 + nt) * 128 + lane * 4]) =
                        *reinterpret_cast<float4*>(acc[mi][nt]);
        }
        __syncthreads();
        if (w < 2) {                       // kgroup 0 adds, writes gates
            float* base = red + w * 1024;
            int g = lane >> 2, tq = lane & 3;
#pragma unroll
            for (int mi = 0; mi < 2; mi++)
#pragma unroll
                for (int nt = 0; nt < 4; nt++) {
                    float4 v = *reinterpret_cast<float4*>(&base[(mi * 4 + nt) * 128 + lane * 4]);
                    float s0 = acc[mi][nt][0] + v.x, s1 = acc[mi][nt][1] + v.y;
                    float s2 = acc[mi][nt][2] + v.z, s3 = acc[mi][nt][3] + v.w;
                    int r = mh * 32 + mi * 16 + g, cc = nt * 8 + tq * 2;
                    *reinterpret_cast<float2*>(&gs[r * 36 + cc]) = make_float2(s0, s1);
                    *reinterpret_cast<float2*>(&gs[(r + 8) * 36 + cc]) = make_float2(s2, s3);
                }
        }
        __syncthreads();

        // --- pointwise: 2 hidden units per thread ---
#pragma unroll
        for (int q = 0; q < 2; q++) {
            int r  = q ? r1 : r0;
            int jl = q ? jl1 : jl0;
            float4 xg = q ? xg1 : xg0;
            float gi = gs[r * 36 + jl * 4 + 0] + xg.x;
            float gf = gs[r * 36 + jl * 4 + 1] + xg.y;
            float go = gs[r * 36 + jl * 4 + 2] + xg.z;
            float gc = gs[r * 36 + jl * 4 + 3] + xg.w;
            float I  = 1.f / (1.f + __expf(-gi));
            float F  = 1.f / (1.f + __expf(-gf));
            float O  = 1.f / (1.f + __expf(-go));
            float Ct = tanhf(gc);
            float Cc = q ? Creg1 : Creg0;
            float Cn = F * Cc + I * Ct;
            float Hn = O * tanhf(Cn);
            if (q) Creg1 = Cn; else Creg0 = Cn;
            float ht = f2tf(Hn);
            Hdst[q ? hfi1 : hfi0] = ht;
            int kg = q ? k1 : k0;
            g_Hs[((size_t)t * BB + r) * HHID + kg] = ht;
            if (t == TT - 1) {
                out[(size_t)MBIG * DD + r * HHID + kg] = Hn;
                out[(size_t)MBIG * DD + BB * HHID + r * HHID + kg] = Cn;
            }
        }

        // --- publish this block's H slice ---
        __threadfence();
        __syncthreads();
        if (tid == 0) atomicAdd(&g_ck[mychunk], 1u);
    }
}

// ---------------- launch ----------------
extern "C" void kernel_launch(void* const* d_in, const int* in_sizes, int n_in,
                              void* d_out, int out_size)
{
    const float* inputs = (const float*)d_in[0];
    const float* H0  = (const float*)d_in[1];
    const float* C0  = (const float*)d_in[2];
    const float* Wxi = (const float*)d_in[3];
    const float* Whi = (const float*)d_in[4];
    const float* bi  = (const float*)d_in[5];
    const float* Wxf = (const float*)d_in[6];
    const float* Whf = (const float*)d_in[7];
    const float* bf_ = (const float*)d_in[8];
    const float* Wxo = (const float*)d_in[9];
    const float* Who = (const float*)d_in[10];
    const float* bo  = (const float*)d_in[11];
    const float* Wxc = (const float*)d_in[12];
    const float* Whc = (const float*)d_in[13];
    const float* bc  = (const float*)d_in[14];
    const float* Whq = (const float*)d_in[15];
    const float* bq  = (const float*)d_in[16];
    float* out = (float*)d_out;

    cudaFuncSetAttribute(lstm_rec, cudaFuncAttributeMaxDynamicSharedMemorySize,
                         SMEM_REC_BYTES);

    prep_kernel<<<4096, 256>>>(Wxi, Wxf, Wxo, Wxc, Whi, Whf, Who, Whc,
                               bi, bf_, bo, bc, Whq, H0);
    gemm_tf32<<<dim3(32, 128), 256>>>(inputs, nullptr, nullptr, 0);   // Xg
    lstm_rec<<<NBLK_REC, 256, SMEM_REC_BYTES>>>(C0, out);             // recurrence
    gemm_tf32<<<dim3(8, 128), 256>>>(nullptr, bq, out, 1);            // outputs
}

// round 4
// speedup vs baseline: 2.6412x; 1.2399x over previous
#include <cuda_runtime.h>
#include <cuda_fp16.h>
#include <cstdint>

#define TT 256
#define BB 64
#define DD 1024
#define HHID 1024
#define NG 4096           // 4*H, gate-interleaved columns (c = j*4 + g)
#define MBIG (TT*BB)      // 16384
#define NBLK_REC 128

// Dynamic smem layout for lstm_rec (bytes):
//   [0, 65536)            Wh slice, fp16 frag-packed (64 KB)
//   [65536, 131072)       A double buffer (2 x 32 KB fp16) ; float scratch for reduction
//   [131072, 140288)      gate staging fp32, stride 36 (64 x 36)
#define SMB_WH   0
#define SMB_ABUF 65536
#define SMB_GS   131072
#define SMEM_REC_BYTES (131072 + 64*36*4)

// ---------------- device scratch ----------------
__device__ float  g_Wx[DD*NG];                 // tf32, interleaved  (16 MB)
__device__ __half g_Whh[HHID*NG];              // fp16, frag-packed  (8 MB)
__device__ float  g_Wq[HHID*DD];               // tf32               (4 MB)
__device__ float  g_b[NG];                     // fp32 packed biases
__device__ float  g_Xg[(size_t)MBIG*NG];       // fp32 gate preacts  (256 MB)
__device__ __half g_Hh[2][BB*HHID];            // fp16 H double buffer, frag-packed
__device__ float  g_Hs[(size_t)MBIG*HHID];     // tf32 H history [t][r][k]
__device__ unsigned g_ck[4];                   // per-chunk publish counters

// ---------------- helpers ----------------
__device__ __forceinline__ float f2tf(float x) {
    unsigned u;
    asm("cvt.rna.tf32.f32 %0, %1;" : "=r"(u) : "f"(x));
    return __uint_as_float(u);
}

__device__ __forceinline__ void mma16(float* c, const unsigned* a, const unsigned* b) {
    asm volatile(
        "mma.sync.aligned.m16n8k16.row.col.f32.f16.f16.f32 "
        "{%0,%1,%2,%3},{%4,%5,%6,%7},{%8,%9},{%0,%1,%2,%3};\n"
        : "+f"(c[0]), "+f"(c[1]), "+f"(c[2]), "+f"(c[3])
        : "r"(a[0]), "r"(a[1]), "r"(a[2]), "r"(a[3]), "r"(b[0]), "r"(b[1]));
}

__device__ __forceinline__ void mma8(float* c, const unsigned* a, const unsigned* b) {
    asm volatile(
        "mma.sync.aligned.m16n8k8.row.col.f32.tf32.tf32.f32 "
        "{%0,%1,%2,%3},{%4,%5,%6,%7},{%8,%9},{%0,%1,%2,%3};\n"
        : "+f"(c[0]), "+f"(c[1]), "+f"(c[2]), "+f"(c[3])
        : "r"(a[0]), "r"(a[1]), "r"(a[2]), "r"(a[3]), "r"(b[0]), "r"(b[1]));
}

__device__ __forceinline__ void cpa16(uint32_t d, const void* s) {
    asm volatile("cp.async.cg.shared.global [%0], [%1], 16;\n" :: "r"(d), "l"(s));
}
#define CPA_COMMIT()  asm volatile("cp.async.commit_group;\n")
#define CPA_WAIT(N)   asm volatile("cp.async.wait_group %0;\n" :: "n"(N))

__device__ __forceinline__ void poll_chunk(int c, unsigned target) {
    if (target == 0u) return;
    const unsigned* p = &g_ck[c];
    unsigned v;
    while (true) {
        asm volatile("ld.acquire.gpu.u32 %0, [%1];" : "=r"(v) : "l"(p));
        if (v >= target) break;
        __nanosleep(32);
    }
}

// fp16 frag index of H element (row r in [0,64), hidden k in [0,1024)) for
// m16n8k16 A fragments, chunked by K=256:
//   chunk = k>>8; uint4 u = ((kb_local*4 + mt)*32 + g8*4 + tq)
//   half pos within uint4 = khalf*4 + half*2 + kp
__device__ __forceinline__ int hfrag16(int r, int k) {
    int c = k >> 8;
    int u = (((k >> 4) & 15) * 4 + (r >> 4)) * 32 + (r & 7) * 4 + ((k >> 1) & 3);
    int pos = ((k >> 3) & 1) * 4 + ((r >> 3) & 1) * 2 + (k & 1);
    return c * 16384 + u * 8 + pos;
}

// ---------------- prep: pack + convert weights, init state ----------------
__global__ void prep_kernel(
    const float* __restrict__ Wxi, const float* __restrict__ Wxf,
    const float* __restrict__ Wxo, const float* __restrict__ Wxc,
    const float* __restrict__ Whi, const float* __restrict__ Whf_,
    const float* __restrict__ Who, const float* __restrict__ Whc,
    const float* __restrict__ bi,  const float* __restrict__ bf_,
    const float* __restrict__ bo,  const float* __restrict__ bc,
    const float* __restrict__ Whq, const float* __restrict__ H0)
{
    int i = blockIdx.x * 256 + threadIdx.x;     // 0 .. 1048575
    {
        float4 v = make_float4(f2tf(Wxi[i]), f2tf(Wxf[i]), f2tf(Wxo[i]), f2tf(Wxc[i]));
        *reinterpret_cast<float4*>(&g_Wx[(size_t)i * 4]) = v;
    }
    // W_h fp16 frag pack: element (k, c=j*4+g), block b=c>>5 owns 32 cols:
    //   halfidx(block) = (((kb*4 + nt)*32 + g8*4 + tq)*2 + khalf)*2 + kp
    {
        int k = i >> 10, j = i & 1023;
        float v[4] = { Whi[i], Whf_[i], Who[i], Whc[i] };
        int kb = k >> 4, khalf = (k >> 3) & 1, tq = (k >> 1) & 3, kp = k & 1;
#pragma unroll
        for (int g = 0; g < 4; g++) {
            int c = j * 4 + g;
            int b = c >> 5, nt = (c >> 3) & 3, g8 = c & 7;
            size_t dst = (size_t)b * 32768 +
                ((((size_t)kb * 4 + nt) * 32 + g8 * 4 + tq) * 2 + khalf) * 2 + kp;
            g_Whh[dst] = __float2half_rn(v[g]);
        }
    }
    g_Wq[i] = f2tf(Whq[i]);
    if (i < HHID) {
        g_b[i * 4 + 0] = bi[i];
        g_b[i * 4 + 1] = bf_[i];
        g_b[i * 4 + 2] = bo[i];
        g_b[i * 4 + 3] = bc[i];
    }
    if (i < BB * HHID) {
        int r = i >> 10, k = i & 1023;
        g_Hh[0][hfrag16(r, k)] = __float2half_rn(H0[i]);
    }
    if (i < 4) g_ck[i] = 0u;    // reset publish counters (every graph replay)
}

// ---------------- big GEMM: C = A(MxK) @ B(KxN) + bias, tf32 MMA -------------
__global__ __launch_bounds__(256, 2) void gemm_tf32(
    const float* __restrict__ Aarg, const float* __restrict__ barg,
    float* __restrict__ Carg, int mode)
{
    __shared__ float As[128][36];
    __shared__ float Bs[32][136];

    const float* A    = mode ? g_Hs : Aarg;
    const float* Bm   = mode ? g_Wq : g_Wx;
    const float* bias = mode ? barg : g_b;
    float*       C    = mode ? Carg : g_Xg;
    const int N = mode ? DD : NG;
    const int K = 1024;
    const int convA = (mode == 0);

    int tid  = threadIdx.x;
    int row0 = blockIdx.y * 128;
    int col0 = blockIdx.x * 128;
    int w = tid >> 5, lane = tid & 31, g = lane >> 2, tq = lane & 3;
    int wm = w & 3, wn = w >> 2;

    float acc[2][8][4];
#pragma unroll
    for (int a = 0; a < 2; a++)
#pragma unroll
        for (int b = 0; b < 8; b++)
#pragma unroll
            for (int c = 0; c < 4; c++) acc[a][b][c] = 0.f;

    for (int kc = 0; kc < K; kc += 32) {
        __syncthreads();
#pragma unroll
        for (int j = 0; j < 4; j++) {
            int idx = tid + j * 256;
            int r = idx >> 3, q = (idx & 7) * 4;
            float4 v = *reinterpret_cast<const float4*>(&A[(size_t)(row0 + r) * K + kc + q]);
            if (convA) { v.x = f2tf(v.x); v.y = f2tf(v.y); v.z = f2tf(v.z); v.w = f2tf(v.w); }
            As[r][q] = v.x; As[r][q + 1] = v.y; As[r][q + 2] = v.z; As[r][q + 3] = v.w;
        }
#pragma unroll
        for (int j = 0; j < 4; j++) {
            int idx = tid + j * 256;
            int r = idx >> 5, q = (idx & 31) * 4;
            float4 v = *reinterpret_cast<const float4*>(&Bm[(size_t)(kc + r) * N + col0 + q]);
            Bs[r][q] = v.x; Bs[r][q + 1] = v.y; Bs[r][q + 2] = v.z; Bs[r][q + 3] = v.w;
        }
        __syncthreads();

        const unsigned* Asu = reinterpret_cast<const unsigned*>(As);
        const unsigned* Bsu = reinterpret_cast<const unsigned*>(Bs);
#pragma unroll
        for (int ks = 0; ks < 32; ks += 8) {
            unsigned af[2][4], bfrag[8][2];
#pragma unroll
            for (int mt = 0; mt < 2; mt++) {
                int r = wm * 32 + mt * 16 + g;
                af[mt][0] = Asu[r * 36 + ks + tq];
                af[mt][1] = Asu[(r + 8) * 36 + ks + tq];
                af[mt][2] = Asu[r * 36 + ks + tq + 4];
                af[mt][3] = Asu[(r + 8) * 36 + ks + tq + 4];
            }
#pragma unroll
            for (int nt = 0; nt < 8; nt++) {
                int c = wn * 64 + nt * 8 + g;
                bfrag[nt][0] = Bsu[(ks + tq) * 136 + c];
                bfrag[nt][1] = Bsu[(ks + tq + 4) * 136 + c];
            }
#pragma unroll
            for (int mt = 0; mt < 2; mt++)
#pragma unroll
                for (int nt = 0; nt < 8; nt++)
                    mma8(acc[mt][nt], af[mt], bfrag[nt]);
        }
    }

#pragma unroll
    for (int mt = 0; mt < 2; mt++) {
        int r = row0 + wm * 32 + mt * 16 + g;
#pragma unroll
        for (int nt = 0; nt < 8; nt++) {
            int c = col0 + wn * 64 + nt * 8 + tq * 2;
            float b0 = bias[c], b1 = bias[c + 1];
            float2 v0 = make_float2(acc[mt][nt][0] + b0, acc[mt][nt][1] + b1);
            float2 v1 = make_float2(acc[mt][nt][2] + b0, acc[mt][nt][3] + b1);
            *reinterpret_cast<float2*>(&C[(size_t)r * N + c]) = v0;
            *reinterpret_cast<float2*>(&C[(size_t)(r + 8) * N + c]) = v1;
        }
    }
}

// ---------------- persistent recurrent kernel (128 blocks, 1/SM) ----------
// fp16 m16n8k16. Per block: 64 rows x 32 gate cols x K=1024, K in 4 chunks of
// 256. Warp w: kgroup=w>>1 (quarter of each chunk's 16 k16-steps), mh=w&1
// (row half). acc = 2 m-tiles x 4 n-tiles -> 4-way k reduction in smem.
__global__ __launch_bounds__(256, 1) void lstm_rec(const float* __restrict__ C0,
                                                   float* __restrict__ out)
{
    extern __shared__ char dsm[];
    __half* whh  = reinterpret_cast<__half*>(dsm + SMB_WH);    // 32768 halves
    __half* abuf = reinterpret_cast<__half*>(dsm + SMB_ABUF);  // 2 x 16384 halves
    float*  red  = reinterpret_cast<float*>(dsm + SMB_ABUF);   // reduction scratch
    float*  gs   = reinterpret_cast<float*>(dsm + SMB_GS);     // 64 x 36

    const int tid = threadIdx.x;
    const int b   = blockIdx.x;
    const int bcol = b * 32;        // gate-column base in [0,4096)
    const int jg0  = b * 8;         // hidden-unit base in [0,1024)
    const int mychunk = b >> 5;     // K-chunk this block's H slice belongs to
    const int lane = tid & 31;
    const int w = tid >> 5;
    const int kgroup = w >> 1;      // 0..3
    const int mh = w & 1;           // row half

    // --- load Wh slice (64 KB) into smem once ---
    {
        const float4* src = reinterpret_cast<const float4*>(g_Whh + (size_t)b * 32768);
        uint32_t dst = (uint32_t)__cvta_generic_to_shared(whh);
#pragma unroll
        for (int i = 0; i < 16; i++)
            cpa16(dst + (tid + i * 256) * 16, src + tid + i * 256);
        CPA_COMMIT();
    }

    // --- per-thread pointwise geometry ---
    const int r0 = tid >> 3,          jl0 = tid & 7;
    const int r1 = (tid + 256) >> 3,  jl1 = tid & 7;
    const int k0 = jg0 + jl0, k1 = jg0 + jl1;
    const int hfi0 = hfrag16(r0, k0), hfi1 = hfrag16(r1, k1);
    float Creg0 = C0[r0 * HHID + k0];
    float Creg1 = C0[r1 * HHID + k1];

    const uint32_t abase = (uint32_t)__cvta_generic_to_shared(abuf);

    for (int t = 0; t < TT; t++) {
        const __half* Hsrc = g_Hh[t & 1];
        __half* Hdst = g_Hh[(t + 1) & 1];
        const unsigned target = 32u * (unsigned)t;

        // Xg prefetch into registers (DRAM, single use)
        float4 xg0 = __ldcg(reinterpret_cast<const float4*>(
            &g_Xg[((size_t)t * BB + r0) * NG + bcol + jl0 * 4]));
        float4 xg1 = __ldcg(reinterpret_cast<const float4*>(
            &g_Xg[((size_t)t * BB + r1) * NG + bcol + jl1 * 4]));

        // issue H chunks 0,1 (32 KB each) after their producers published
#pragma unroll
        for (int c = 0; c < 2; c++) {
            poll_chunk(c, target);
            const float4* src = reinterpret_cast<const float4*>(Hsrc + c * 16384);
            uint32_t dst = abase + (uint32_t)(c & 1) * 32768u;
#pragma unroll
            for (int i = 0; i < 8; i++)
                cpa16(dst + (tid + i * 256) * 16, src + tid + i * 256);
            CPA_COMMIT();
        }

        float acc[2][4][4];
#pragma unroll
        for (int a = 0; a < 2; a++)
#pragma unroll
            for (int n = 0; n < 4; n++)
#pragma unroll
                for (int e = 0; e < 4; e++) acc[a][n][e] = 0.f;

#pragma unroll
        for (int c = 0; c < 4; c++) {
            if (c < 3) { CPA_WAIT(1); } else { CPA_WAIT(0); }
            __syncthreads();
            const uint4* Ap = reinterpret_cast<const uint4*>(abuf + (c & 1) * 16384);
            const uint2* Bp = reinterpret_cast<const uint2*>(whh) + (size_t)(c * 16) * 128;
#pragma unroll
            for (int kk = 0; kk < 4; kk++) {
                int kbl = kgroup * 4 + kk;
                uint4 a0 = Ap[(kbl * 4 + mh * 2 + 0) * 32 + lane];
                uint4 a1 = Ap[(kbl * 4 + mh * 2 + 1) * 32 + lane];
                unsigned af0[4] = { a0.x, a0.y, a0.z, a0.w };
                unsigned af1[4] = { a1.x, a1.y, a1.z, a1.w };
#pragma unroll
                for (int nt = 0; nt < 4; nt++) {
                    uint2 bv = Bp[(kbl * 4 + nt) * 32 + lane];
                    mma16(acc[0][nt], af0, reinterpret_cast<unsigned*>(&bv));
                    mma16(acc[1][nt], af1, reinterpret_cast<unsigned*>(&bv));
                }
            }
            __syncthreads();
            if (c + 2 < 4) {
                int cn = c + 2;
                poll_chunk(cn, target);
                const float4* src = reinterpret_cast<const float4*>(Hsrc + cn * 16384);
                uint32_t dst = abase + (uint32_t)(cn & 1) * 32768u;
#pragma unroll
                for (int i = 0; i < 8; i++)
                    cpa16(dst + (tid + i * 256) * 16, src + tid + i * 256);
                CPA_COMMIT();
            }
        }

        // --- K-group reduction: 4 partials -> 1 (reuse abuf as float scratch) ---
        if (w >= 4) {                      // kgroups 2,3 store (slots w-4 = 0..3)
            float* base = red + (w - 4) * 1024;
#pragma unroll
            for (int mi = 0; mi < 2; mi++)
#pragma unroll
                for (int nt = 0; nt < 4; nt++)
                    *reinterpret_cast<float4*>(&base[(mi * 4 + nt) * 128 + lane * 4]) =
                        *reinterpret_cast<float4*>(acc[mi][nt]);
        }
        __syncthreads();
        if (w < 4) {                       // kgroups 0,1 add partner (slot w)
            float* base = red + w * 1024;
#pragma unroll
            for (int mi = 0; mi < 2; mi++)
#pragma unroll
                for (int nt = 0; nt < 4; nt++) {
                    float4 v = *reinterpret_cast<float4*>(&base[(mi * 4 + nt) * 128 + lane * 4]);
                    acc[mi][nt][0] += v.x; acc[mi][nt][1] += v.y;
                    acc[mi][nt][2] += v.z; acc[mi][nt][3] += v.w;
                }
        }
        __syncthreads();
        if (w == 2 || w == 3) {            // kgroup 1 stores (slots w-2 = 0,1)
            float* base = red + (w - 2) * 1024;
#pragma unroll
            for (int mi = 0; mi < 2; mi++)
#pragma unroll
                for (int nt = 0; nt < 4; nt++)
                    *reinterpret_cast<float4*>(&base[(mi * 4 + nt) * 128 + lane * 4]) =
                        *reinterpret_cast<float4*>(acc[mi][nt]);
        }
        __syncthreads();
        if (w < 2) {                       // kgroup 0 adds, writes gates
            float* base = red + w * 1024;
            int g = lane >> 2, tq = lane & 3;
#pragma unroll
            for (int mi = 0; mi < 2; mi++)
#pragma unroll
                for (int nt = 0; nt < 4; nt++) {
                    float4 v = *reinterpret_cast<float4*>(&base[(mi * 4 + nt) * 128 + lane * 4]);
                    float s0 = acc[mi][nt][0] + v.x, s1 = acc[mi][nt][1] + v.y;
                    float s2 = acc[mi][nt][2] + v.z, s3 = acc[mi][nt][3] + v.w;
                    int r = mh * 32 + mi * 16 + g, cc = nt * 8 + tq * 2;
                    *reinterpret_cast<float2*>(&gs[r * 36 + cc]) = make_float2(s0, s1);
                    *reinterpret_cast<float2*>(&gs[(r + 8) * 36 + cc]) = make_float2(s2, s3);
                }
        }
        __syncthreads();

        // --- pointwise: 2 hidden units per thread ---
#pragma unroll
        for (int q = 0; q < 2; q++) {
            int r  = q ? r1 : r0;
            int jl = q ? jl1 : jl0;
            float4 xg = q ? xg1 : xg0;
            float gi = gs[r * 36 + jl * 4 + 0] + xg.x;
            float gf = gs[r * 36 + jl * 4 + 1] + xg.y;
            float go = gs[r * 36 + jl * 4 + 2] + xg.z;
            float gc = gs[r * 36 + jl * 4 + 3] + xg.w;
            float I  = 1.f / (1.f + __expf(-gi));
            float F  = 1.f / (1.f + __expf(-gf));
            float O  = 1.f / (1.f + __expf(-go));
            float Ct = tanhf(gc);
            float Cc = q ? Creg1 : Creg0;
            float Cn = F * Cc + I * Ct;
            float Hn = O * tanhf(Cn);
            if (q) Creg1 = Cn; else Creg0 = Cn;
            Hdst[q ? hfi1 : hfi0] = __float2half_rn(Hn);
            int kg = q ? k1 : k0;
            g_Hs[((size_t)t * BB + r) * HHID + kg] = f2tf(Hn);
            if (t == TT - 1) {
                out[(size_t)MBIG * DD + r * HHID + kg] = Hn;
                out[(size_t)MBIG * DD + BB * HHID + r * HHID + kg] = Cn;
            }
        }

        // --- publish this block's H slice ---
        __threadfence();
        __syncthreads();
        if (tid == 0) atomicAdd(&g_ck[mychunk], 1u);
    }
}

// ---------------- launch ----------------
extern "C" void kernel_launch(void* const* d_in, const int* in_sizes, int n_in,
                              void* d_out, int out_size)
{
    const float* inputs = (const float*)d_in[0];
    const float* H0  = (const float*)d_in[1];
    const float* C0  = (const float*)d_in[2];
    const float* Wxi = (const float*)d_in[3];
    const float* Whi = (const float*)d_in[4];
    const float* bi  = (const float*)d_in[5];
    const float* Wxf = (const float*)d_in[6];
    const float* Whf = (const float*)d_in[7];
    const float* bf_ = (const float*)d_in[8];
    const float* Wxo = (const float*)d_in[9];
    const float* Who = (const float*)d_in[10];
    const float* bo  = (const float*)d_in[11];
    const float* Wxc = (const float*)d_in[12];
    const float* Whc = (const float*)d_in[13];
    const float* bc  = (const float*)d_in[14];
    const float* Whq = (const float*)d_in[15];
    const float* bq  = (const float*)d_in[16];
    float* out = (float*)d_out;

    cudaFuncSetAttribute(lstm_rec, cudaFuncAttributeMaxDynamicSharedMemorySize,
                         SMEM_REC_BYTES);

    prep_kernel<<<4096, 256>>>(Wxi, Wxf, Wxo, Wxc, Whi, Whf, Who, Whc,
                               bi, bf_, bo, bc, Whq, H0);
    gemm_tf32<<<dim3(32, 128), 256>>>(inputs, nullptr, nullptr, 0);   // Xg
    lstm_rec<<<NBLK_REC, 256, SMEM_REC_BYTES>>>(C0, out);             // recurrence
    gemm_tf32<<<dim3(8, 128), 256>>>(nullptr, bq, out, 1);            // outputs
}